// round 13
// baseline (speedup 1.0000x reference)
#include <cuda_runtime.h>
#include <cuda_fp16.h>
#include <math.h>

#define Bv   4
#define Tn   2048
#define Cn   384
#define Hn   6
#define HSn  64
#define BTn  8192
#define BHn  24
#define C4n  1536

// ------------------------- scratch (static device globals) -------------------------
__device__ __half g_h[BTn * Cn];                     // LN output fp16
__device__ __half g_qh[BHn * Tn * HSn];              // Q fp16 [bh][t][d]
__device__ __half g_kh[BHn * Tn * HSn];              // K fp16 [bh][s][d]
__device__ float  g_v[BHn * Tn * HSn];               // V fp32 [bh][s][d]
__device__ __half g_vt[BHn * HSn * Tn];              // V'/Z transposed fp16 [bh][d][s]
__device__ float  g_z[BHn * Tn];                     // per-key sum of exp(S)
__device__ __half g_swt[(size_t)BHn * Tn * Tn];      // weights exp(S) fp16, layout [bh][t][s]
__device__ float  g_attn[BTn * Cn];                  // attention out fp32 (RED target)
__device__ float  g_x1[BTn * Cn];
__device__ __half g_f1h[BTn * C4n];                  // MLP hidden fp16
// fp16 transposed weights Bt[N][K]
__device__ __half g_wqkvt[3 * Hn * HSn * Cn];        // [sel][h][d][c] == [1152][384]
__device__ __half g_wpt[Cn * Cn];                    // [n][k]
__device__ __half g_w1t[C4n * Cn];                   // [n 1536][k 384]
__device__ __half g_w2t[Cn * C4n];                   // [n 384][k 1536]

#define SCALE 0.05103103630798287f       // 384^-0.5

// ------------------------- mma / async helpers -------------------------
__device__ __forceinline__ void mma16(float* c, const unsigned* a, const unsigned* b) {
    asm volatile(
        "mma.sync.aligned.m16n8k16.row.col.f32.f16.f16.f32 "
        "{%0,%1,%2,%3}, {%4,%5,%6,%7}, {%8,%9}, {%0,%1,%2,%3};\n"
        : "+f"(c[0]), "+f"(c[1]), "+f"(c[2]), "+f"(c[3])
        : "r"(a[0]), "r"(a[1]), "r"(a[2]), "r"(a[3]), "r"(b[0]), "r"(b[1]));
}

__device__ __forceinline__ void red2(float* p, float x, float y) {
    asm volatile("red.global.add.v2.f32 [%0], {%1,%2};" :: "l"(p), "f"(x), "f"(y) : "memory");
}

__device__ __forceinline__ void cp16(void* dst, const void* src) {
    unsigned d = (unsigned)__cvta_generic_to_shared(dst);
    asm volatile("cp.async.cg.shared.global [%0], [%1], 16;" :: "r"(d), "l"(src) : "memory");
}
#define CP_COMMIT() asm volatile("cp.async.commit_group;" ::: "memory")
#define CP_WAIT1()  asm volatile("cp.async.wait_group 1;" ::: "memory")
#define CP_WAIT0()  asm volatile("cp.async.wait_group 0;" ::: "memory")

// ------------------------- weight transpose+fp16 -------------------------
__global__ void transpose16(const float* __restrict__ in, __half* __restrict__ out,
                            int K, int N) {
    __shared__ float t[32][33];
    int n0 = blockIdx.x * 32, k0 = blockIdx.y * 32;
    int tx = threadIdx.x, ty = threadIdx.y;
    #pragma unroll
    for (int i = 0; i < 4; i++)
        t[ty + i * 8][tx] = in[(size_t)(k0 + ty + i * 8) * N + n0 + tx];
    __syncthreads();
    #pragma unroll
    for (int i = 0; i < 4; i++)
        out[(size_t)(n0 + ty + i * 8) * K + k0 + tx] = __float2half(t[tx][ty + i * 8]);
}

__global__ void qkvt16(const float* __restrict__ wq, const float* __restrict__ wk,
                       const float* __restrict__ wv) {
    __shared__ float t[32][33];
    int sel = blockIdx.z / Hn, hh = blockIdx.z % Hn;
    const float* in = (sel == 0 ? wq : sel == 1 ? wk : wv) + hh * Cn * HSn;
    __half* out = g_wqkvt + (size_t)blockIdx.z * HSn * Cn;
    int n0 = blockIdx.x * 32, k0 = blockIdx.y * 32;
    int tx = threadIdx.x, ty = threadIdx.y;
    #pragma unroll
    for (int i = 0; i < 4; i++)
        t[ty + i * 8][tx] = in[(size_t)(k0 + ty + i * 8) * HSn + n0 + tx];
    __syncthreads();
    #pragma unroll
    for (int i = 0; i < 4; i++)
        out[(size_t)(n0 + ty + i * 8) * Cn + k0 + tx] = __float2half(t[tx][ty + i * 8]);
}

// ------------------------- LayerNorm (fp32 in, fp16 out) -------------------------
__global__ void ln_kernel(const float* __restrict__ in, const float* __restrict__ gamma,
                          const float* __restrict__ beta, __half* __restrict__ out) {
    int row = blockIdx.x;
    int tid = threadIdx.x;
    const float* p = in + row * Cn;
    float v0 = p[tid], v1 = p[tid + 128], v2 = p[tid + 256];
    float s = v0 + v1 + v2;
    __shared__ float red[4];
    #pragma unroll
    for (int o = 16; o > 0; o >>= 1) s += __shfl_xor_sync(0xffffffffu, s, o);
    if ((tid & 31) == 0) red[tid >> 5] = s;
    __syncthreads();
    float mean = (red[0] + red[1] + red[2] + red[3]) * (1.0f / Cn);
    __syncthreads();
    float d0 = v0 - mean, d1 = v1 - mean, d2 = v2 - mean;
    float q = d0 * d0 + d1 * d1 + d2 * d2;
    #pragma unroll
    for (int o = 16; o > 0; o >>= 1) q += __shfl_xor_sync(0xffffffffu, q, o);
    if ((tid & 31) == 0) red[tid >> 5] = q;
    __syncthreads();
    float var = (red[0] + red[1] + red[2] + red[3]) * (1.0f / Cn);
    float r = rsqrtf(var + 1e-5f);
    __half* o = out + row * Cn;
    o[tid]       = __float2half(d0 * r * gamma[tid]       + beta[tid]);
    o[tid + 128] = __float2half(d1 * r * gamma[tid + 128] + beta[tid + 128]);
    o[tid + 256] = __float2half(d2 * r * gamma[tid + 256] + beta[tid + 256]);
}

// ------------------------- fp16 GEMM 128x128: C[M,N] = A[M,K] @ Bt[N,K]^T -------------------------
// 512 threads, 16 warps (4m x 4n), warp tile 32x32, BK=64.
// AF32: A is fp32, converted to half during smem stage.
// EPI 0: bias+relu -> half. EPI 1: bias+resid -> float.
template <int EPI, int AF32>
__global__ __launch_bounds__(512)
void gemm128(const void* __restrict__ Ain, const __half* __restrict__ Bt,
             const float* __restrict__ bias, const float* __restrict__ resid,
             void* __restrict__ Co, int N, int K) {
    __shared__ __half As[128][72];
    __shared__ __half Bs[128][72];
    int m0 = blockIdx.y * 128, n0 = blockIdx.x * 128;
    int tid = threadIdx.x, l = tid & 31, w = tid >> 5;
    int wm = (w & 3) * 32, wn = (w >> 2) * 32;
    int g = l >> 2, tg = l & 3;
    const unsigned* A32 = (const unsigned*)As;
    const unsigned* B32 = (const unsigned*)Bs;
    float acc[2][4][4] = {};
    for (int k0 = 0; k0 < K; k0 += 64) {
        if (AF32) {
            const float* Af = (const float*)Ain;
            #pragma unroll
            for (int i = 0; i < 4; i++) {
                int idx = tid + i * 512;
                int r = idx >> 4, c4 = (idx & 15) * 4;
                float4 v = *(const float4*)&Af[(size_t)(m0 + r) * K + k0 + c4];
                *(__half2*)&As[r][c4]     = __floats2half2_rn(v.x, v.y);
                *(__half2*)&As[r][c4 + 2] = __floats2half2_rn(v.z, v.w);
            }
        } else {
            const __half* Ah = (const __half*)Ain;
            #pragma unroll
            for (int i = 0; i < 2; i++) {
                int idx = tid + i * 512;
                int r = idx >> 3, cv = (idx & 7) * 8;
                *(float4*)&As[r][cv] = *(const float4*)&Ah[(size_t)(m0 + r) * K + k0 + cv];
            }
        }
        #pragma unroll
        for (int i = 0; i < 2; i++) {
            int idx = tid + i * 512;
            int r = idx >> 3, cv = (idx & 7) * 8;
            *(float4*)&Bs[r][cv] = *(const float4*)&Bt[(size_t)(n0 + r) * K + k0 + cv];
        }
        __syncthreads();
        #pragma unroll
        for (int kk = 0; kk < 64; kk += 16) {
            int kw = kk >> 1;
            unsigned a[2][4], b[4][2];
            #pragma unroll
            for (int im = 0; im < 2; im++) {
                int r = wm + im * 16;
                a[im][0] = A32[(r + g) * 36 + kw + tg];
                a[im][1] = A32[(r + 8 + g) * 36 + kw + tg];
                a[im][2] = A32[(r + g) * 36 + kw + 4 + tg];
                a[im][3] = A32[(r + 8 + g) * 36 + kw + 4 + tg];
            }
            #pragma unroll
            for (int jn = 0; jn < 4; jn++) {
                int c = wn + jn * 8;
                b[jn][0] = B32[(c + g) * 36 + kw + tg];
                b[jn][1] = B32[(c + g) * 36 + kw + 4 + tg];
            }
            #pragma unroll
            for (int im = 0; im < 2; im++)
                #pragma unroll
                for (int jn = 0; jn < 4; jn++) mma16(acc[im][jn], a[im], b[jn]);
        }
        __syncthreads();
    }
    #pragma unroll
    for (int im = 0; im < 2; im++) {
        #pragma unroll
        for (int hh = 0; hh < 2; hh++) {
            int r0 = m0 + wm + im * 16 + g + hh * 8;
            #pragma unroll
            for (int jn = 0; jn < 4; jn++) {
                int c = n0 + wn + jn * 8 + tg * 2;
                float v0 = acc[im][jn][hh * 2]     + bias[c];
                float v1 = acc[im][jn][hh * 2 + 1] + bias[c + 1];
                if (EPI == 0) {
                    v0 = fmaxf(v0, 0.f); v1 = fmaxf(v1, 0.f);
                    *(__half2*)&((__half*)Co)[(size_t)r0 * N + c] = __floats2half2_rn(v0, v1);
                } else {
                    v0 += resid[(size_t)r0 * N + c];
                    v1 += resid[(size_t)r0 * N + c + 1];
                    *(float2*)&((float*)Co)[(size_t)r0 * N + c] = make_float2(v0, v1);
                }
            }
        }
    }
}

// ------------------------- QKV as one GEMM [8192,384] @ [1152,384]^T, routed epilogue -------------------------
__global__ __launch_bounds__(512)
void qkv128() {
    __shared__ __half As[128][72];
    __shared__ __half Bs[128][72];
    int m0 = blockIdx.y * 128, n0 = blockIdx.x * 128;
    int tid = threadIdx.x, l = tid & 31, w = tid >> 5;
    int wm = (w & 3) * 32, wn = (w >> 2) * 32;
    int g = l >> 2, tg = l & 3;
    const unsigned* A32 = (const unsigned*)As;
    const unsigned* B32 = (const unsigned*)Bs;
    float acc[2][4][4] = {};
    for (int k0 = 0; k0 < Cn; k0 += 64) {
        #pragma unroll
        for (int i = 0; i < 2; i++) {
            int idx = tid + i * 512;
            int r = idx >> 3, cv = (idx & 7) * 8;
            *(float4*)&As[r][cv] = *(const float4*)&g_h[(size_t)(m0 + r) * Cn + k0 + cv];
            *(float4*)&Bs[r][cv] = *(const float4*)&g_wqkvt[(size_t)(n0 + r) * Cn + k0 + cv];
        }
        __syncthreads();
        #pragma unroll
        for (int kk = 0; kk < 64; kk += 16) {
            int kw = kk >> 1;
            unsigned a[2][4], b[4][2];
            #pragma unroll
            for (int im = 0; im < 2; im++) {
                int r = wm + im * 16;
                a[im][0] = A32[(r + g) * 36 + kw + tg];
                a[im][1] = A32[(r + 8 + g) * 36 + kw + tg];
                a[im][2] = A32[(r + g) * 36 + kw + 4 + tg];
                a[im][3] = A32[(r + 8 + g) * 36 + kw + 4 + tg];
            }
            #pragma unroll
            for (int jn = 0; jn < 4; jn++) {
                int c = wn + jn * 8;
                b[jn][0] = B32[(c + g) * 36 + kw + tg];
                b[jn][1] = B32[(c + g) * 36 + kw + 4 + tg];
            }
            #pragma unroll
            for (int im = 0; im < 2; im++)
                #pragma unroll
                for (int jn = 0; jn < 4; jn++) mma16(acc[im][jn], a[im], b[jn]);
        }
        __syncthreads();
    }
    int nbase = n0 + wn;
    int sel = nbase / (Hn * HSn);
    int nn  = nbase % (Hn * HSn);
    int hh  = nn / HSn;
    int dbase = nn % HSn;
    #pragma unroll
    for (int im = 0; im < 2; im++) {
        #pragma unroll
        for (int hf = 0; hf < 2; hf++) {
            int m = m0 + wm + im * 16 + g + hf * 8;
            int b = m >> 11, t = m & (Tn - 1);
            size_t rowoff = ((size_t)(b * Hn + hh) * Tn + t) * HSn;
            if (sel == 2) {
                float* orow = g_v + rowoff;
                #pragma unroll
                for (int jn = 0; jn < 4; jn++) {
                    int d = dbase + jn * 8 + tg * 2;
                    *(float2*)&orow[d] =
                        make_float2(acc[im][jn][hf * 2], acc[im][jn][hf * 2 + 1]);
                }
            } else {
                __half* orow = (sel == 0 ? g_qh : g_kh) + rowoff;
                #pragma unroll
                for (int jn = 0; jn < 4; jn++) {
                    int d = dbase + jn * 8 + tg * 2;
                    *(__half2*)&orow[d] =
                        __floats2half2_rn(acc[im][jn][hf * 2], acc[im][jn][hf * 2 + 1]);
                }
            }
        }
    }
}

// ------------------------- wsum16: Wt[t][s] = exp(scale*Q[t]·K[s]) fp16, Z[s] row sums -------------------------
// Smem-staged coalesced weight store. Staging stride 136 halves (272B, 16B-aligned).
#define WST 136
__global__ __launch_bounds__(256)
void wsum16() {
    __shared__ __half sm[2 * 128 * 72];          // Qs | Ks, later reused as Wst[128][WST]
    __half (*Qs)[72] = (__half(*)[72])sm;
    __half (*Ks)[72] = (__half(*)[72])(sm + 128 * 72);
    __half* Wst = sm;                            // [128][WST] = 17408 halfs <= 18432
    int tT = blockIdx.x, sT = blockIdx.y, bh = blockIdx.z;
    if (tT < sT) return;
    const __half* Qp = g_qh + (size_t)bh * Tn * HSn + (size_t)tT * 128 * HSn;
    const __half* Kp = g_kh + (size_t)bh * Tn * HSn + (size_t)sT * 128 * HSn;
    __half* Wr = g_swt + (size_t)bh * Tn * Tn;
    int tid = threadIdx.x, l = tid & 31, w = tid >> 5;
    int g = l >> 2, tg = l & 3;
    #pragma unroll
    for (int i = 0; i < 4; i++) {
        int idx = tid + i * 256;
        int r = idx >> 3, cv = (idx & 7) * 8;
        *(float4*)&Qs[r][cv] = *(const float4*)&Qp[(size_t)r * HSn + cv];
        *(float4*)&Ks[r][cv] = *(const float4*)&Kp[(size_t)r * HSn + cv];
    }
    __syncthreads();
    int wm = (w & 3) * 32, wn = (w >> 2) * 64;
    const unsigned* Q32 = (const unsigned*)Qs;
    const unsigned* K32 = (const unsigned*)Ks;
    float acc[2][8][4] = {};
    #pragma unroll
    for (int kk = 0; kk < 64; kk += 16) {
        int kw = kk >> 1;
        unsigned a[2][4], b[8][2];
        #pragma unroll
        for (int im = 0; im < 2; im++) {
            int r = wm + im * 16;
            a[im][0] = Q32[(r + g) * 36 + kw + tg];
            a[im][1] = Q32[(r + 8 + g) * 36 + kw + tg];
            a[im][2] = Q32[(r + g) * 36 + kw + 4 + tg];
            a[im][3] = Q32[(r + 8 + g) * 36 + kw + 4 + tg];
        }
        #pragma unroll
        for (int jn = 0; jn < 8; jn++) {
            int c = wn + jn * 8;
            b[jn][0] = K32[(c + g) * 36 + kw + tg];
            b[jn][1] = K32[(c + g) * 36 + kw + 4 + tg];
        }
        #pragma unroll
        for (int im = 0; im < 2; im++)
            #pragma unroll
            for (int jn = 0; jn < 8; jn++) mma16(acc[im][jn], a[im], b[jn]);
    }
    __syncthreads();    // Q/K smem dead; safe to reuse as staging
    bool diag = (tT == sT);
    #pragma unroll
    for (int jn = 0; jn < 8; jn++) {
        int s_loc = wn + jn * 8 + 2 * tg;
        int s_glob = sT * 128 + s_loc;
        float z0 = 0.f, z1 = 0.f;
        #pragma unroll
        for (int im = 0; im < 2; im++) {
            #pragma unroll
            for (int hh = 0; hh < 2; hh++) {
                int t_loc = wm + im * 16 + g + hh * 8;
                int t_glob = tT * 128 + t_loc;
                float e0 = __expf(acc[im][jn][hh * 2]     * SCALE);
                float e1 = __expf(acc[im][jn][hh * 2 + 1] * SCALE);
                if (diag) {
                    if (t_glob < s_glob)     e0 = 0.f;
                    if (t_glob < s_glob + 1) e1 = 0.f;
                }
                *(__half2*)&Wst[t_loc * WST + s_loc] = __floats2half2_rn(e0, e1);
                z0 += e0; z1 += e1;
            }
        }
        z0 += __shfl_xor_sync(0xffffffffu, z0, 4);
        z1 += __shfl_xor_sync(0xffffffffu, z1, 4);
        z0 += __shfl_xor_sync(0xffffffffu, z0, 8);
        z1 += __shfl_xor_sync(0xffffffffu, z1, 8);
        z0 += __shfl_xor_sync(0xffffffffu, z0, 16);
        z1 += __shfl_xor_sync(0xffffffffu, z1, 16);
        if (g == 0) red2(&g_z[bh * Tn + s_glob], z0, z1);
    }
    __syncthreads();
    // coalesced copy out: 128 rows x 128 halfs (256B); 2 threads per row, 8 float4 each
    {
        int trow = tid >> 1;
        int coff = (tid & 1) * 64;
        __half* dst = Wr + (size_t)(tT * 128 + trow) * Tn + sT * 128 + coff;
        const __half* src = Wst + trow * WST + coff;
        #pragma unroll
        for (int i = 0; i < 8; i++)
            *(float4*)&dst[i * 8] = *(const float4*)&src[i * 8];
    }
}

// ------------------------- vscale_t: Vt[d][s] = fp16( V[s][d] / Z[s] ) -------------------------
__global__ void vscale_t() {
    __shared__ float tile[128][65];
    int s0 = blockIdx.x * 128, bh = blockIdx.y;
    int tid = threadIdx.x;
    const float* Vb = g_v + ((size_t)bh * Tn + s0) * HSn;
    #pragma unroll
    for (int i = 0; i < 8; i++) {
        int idx = tid + i * 256;
        int r = idx >> 4, cv = (idx & 15) * 4;
        float inv = __fdividef(1.0f, g_z[bh * Tn + s0 + r]);
        float4 v = *(const float4*)&Vb[(size_t)r * HSn + cv];
        tile[r][cv + 0] = v.x * inv; tile[r][cv + 1] = v.y * inv;
        tile[r][cv + 2] = v.z * inv; tile[r][cv + 3] = v.w * inv;
    }
    __syncthreads();
    #pragma unroll
    for (int i = 0; i < 16; i++) {
        int idx = tid + i * 256;
        int d = idx >> 6, sp = idx & 63;
        __half2 h = __floats2half2_rn(tile[2 * sp][d], tile[2 * sp + 1][d]);
        *(__half2*)&g_vt[((size_t)bh * HSn + d) * Tn + s0 + 2 * sp] = h;
    }
}

// ------------------------- av16: out[t][d] = sum_s Wt[t][s] * Vt[d][s], cp.async double-buffered -------------------------
#define WTILE (128 * 72)
#define VTILE (64 * 72)
__global__ __launch_bounds__(256, 2)
void av16() {
    extern __shared__ __half smav[];
    __half* Wb[2] = {smav, smav + WTILE};
    __half* Vb[2] = {smav + 2 * WTILE, smav + 2 * WTILE + VTILE};
    int tT = blockIdx.x, sc = blockIdx.y, bh = blockIdx.z;
    int t0 = tT * 128;
    int sBase = sc * 256;
    if (sBase >= t0 + 128) return;
    int limit = min(sBase + 256, t0 + 128);
    int nch = (limit - sBase) >> 6;
    int b = bh / Hn, h = bh % Hn;
    const __half* Wg = g_swt + (size_t)bh * Tn * Tn;
    const __half* Vg = g_vt + (size_t)bh * HSn * Tn;
    int tid = threadIdx.x, l = tid & 31, w = tid >> 5;
    int g = l >> 2, tg = l & 3;
    int wm = (w & 3) * 32, wn = (w >> 2) * 32;
    float acc[2][4][4] = {};
    {
        int s0 = sBase;
        #pragma unroll
        for (int i = 0; i < 4; i++) {
            int idx = tid + i * 256;
            int r = idx >> 3, cv = (idx & 7) * 8;
            cp16(Wb[0] + r * 72 + cv, &Wg[(size_t)(t0 + r) * Tn + s0 + cv]);
        }
        #pragma unroll
        for (int i = 0; i < 2; i++) {
            int idx = tid + i * 256;
            int r = idx >> 3, cv = (idx & 7) * 8;
            cp16(Vb[0] + r * 72 + cv, &Vg[(size_t)r * Tn + s0 + cv]);
        }
        CP_COMMIT();
    }
    for (int j = 0; j < nch; j++) {
        if (j + 1 < nch) {
            int s0 = sBase + (j + 1) * 64, buf = (j + 1) & 1;
            #pragma unroll
            for (int i = 0; i < 4; i++) {
                int idx = tid + i * 256;
                int r = idx >> 3, cv = (idx & 7) * 8;
                cp16(Wb[buf] + r * 72 + cv, &Wg[(size_t)(t0 + r) * Tn + s0 + cv]);
            }
            #pragma unroll
            for (int i = 0; i < 2; i++) {
                int idx = tid + i * 256;
                int r = idx >> 3, cv = (idx & 7) * 8;
                cp16(Vb[buf] + r * 72 + cv, &Vg[(size_t)r * Tn + s0 + cv]);
            }
            CP_COMMIT();
            CP_WAIT1();
        } else {
            CP_WAIT0();
        }
        __syncthreads();
        const unsigned* W32 = (const unsigned*)Wb[j & 1];
        const unsigned* V32 = (const unsigned*)Vb[j & 1];
        #pragma unroll
        for (int kk = 0; kk < 64; kk += 16) {
            int kw = kk >> 1;
            unsigned a[2][4], bf[4][2];
            #pragma unroll
            for (int im = 0; im < 2; im++) {
                int r = wm + im * 16;
                a[im][0] = W32[(r + g) * 36 + kw + tg];
                a[im][1] = W32[(r + 8 + g) * 36 + kw + tg];
                a[im][2] = W32[(r + g) * 36 + kw + 4 + tg];
                a[im][3] = W32[(r + 8 + g) * 36 + kw + 4 + tg];
            }
            #pragma unroll
            for (int jn = 0; jn < 4; jn++) {
                int c = wn + jn * 8;
                bf[jn][0] = V32[(c + g) * 36 + kw + tg];
                bf[jn][1] = V32[(c + g) * 36 + kw + 4 + tg];
            }
            #pragma unroll
            for (int im = 0; im < 2; im++)
                #pragma unroll
                for (int jn = 0; jn < 4; jn++) mma16(acc[im][jn], a[im], bf[jn]);
        }
        __syncthreads();
    }
    #pragma unroll
    for (int im = 0; im < 2; im++) {
        #pragma unroll
        for (int hh = 0; hh < 2; hh++) {
            int t = t0 + wm + im * 16 + g + hh * 8;
            float* orow = g_attn + (size_t)(b * Tn + t) * Cn + h * HSn;
            #pragma unroll
            for (int jn = 0; jn < 4; jn++) {
                int d = wn + jn * 8 + tg * 2;
                red2(&orow[d], acc[im][jn][hh * 2], acc[im][jn][hh * 2 + 1]);
            }
        }
    }
}

// ------------------------- launch -------------------------
extern "C" void kernel_launch(void* const* d_in, const int* in_sizes, int n_in,
                              void* d_out, int out_size) {
    const float* x      = (const float*)d_in[0];
    const float* wq     = (const float*)d_in[1];
    const float* wk     = (const float*)d_in[2];
    const float* wv     = (const float*)d_in[3];
    const float* w_proj = (const float*)d_in[4];
    const float* b_proj = (const float*)d_in[5];
    const float* w1     = (const float*)d_in[6];
    const float* b1     = (const float*)d_in[7];
    const float* w2     = (const float*)d_in[8];
    const float* b2     = (const float*)d_in[9];
    const float* g1     = (const float*)d_in[10];
    const float* be1    = (const float*)d_in[11];
    const float* g2     = (const float*)d_in[12];
    const float* be2    = (const float*)d_in[13];
    float* out = (float*)d_out;

    __half *p_h, *p_f1h, *p_wpt, *p_w1t, *p_w2t;
    float *p_x1, *p_attn, *p_z;
    cudaGetSymbolAddress((void**)&p_h,     g_h);
    cudaGetSymbolAddress((void**)&p_x1,    g_x1);
    cudaGetSymbolAddress((void**)&p_attn,  g_attn);
    cudaGetSymbolAddress((void**)&p_f1h,   g_f1h);
    cudaGetSymbolAddress((void**)&p_z,     g_z);
    cudaGetSymbolAddress((void**)&p_wpt,   g_wpt);
    cudaGetSymbolAddress((void**)&p_w1t,   g_w1t);
    cudaGetSymbolAddress((void**)&p_w2t,   g_w2t);

    int smemAV = (2 * WTILE + 2 * VTILE) * (int)sizeof(__half);   // 55296
    cudaFuncSetAttribute(av16, cudaFuncAttributeMaxDynamicSharedMemorySize, smemAV);

    dim3 tb(32, 8);
    // 0. zero accumulators + weight transposes
    cudaMemsetAsync(p_z, 0, (size_t)BHn * Tn * sizeof(float));
    cudaMemsetAsync(p_attn, 0, (size_t)BTn * Cn * sizeof(float));
    qkvt16<<<dim3(HSn / 32, Cn / 32, 18), tb>>>(wq, wk, wv);
    transpose16<<<dim3(Cn / 32, Cn / 32), tb>>>(w_proj, p_wpt, Cn, Cn);
    transpose16<<<dim3(C4n / 32, Cn / 32), tb>>>(w1, p_w1t, Cn, C4n);
    transpose16<<<dim3(Cn / 32, C4n / 32), tb>>>(w2, p_w2t, C4n, Cn);
    // 1. LN1 -> fp16
    ln_kernel<<<BTn, 128>>>(x, g1, be1, p_h);
    // 2. QKV as one 128x128 GEMM with routed epilogue
    qkv128<<<dim3(9, BTn / 128), 512>>>();
    // 3. Weights Wt[t][s] fp16 + Z row sums (coalesced smem-staged store)
    wsum16<<<dim3(Tn / 128, Tn / 128, BHn), 256>>>();
    // 4. V'/Z transpose fp16
    vscale_t<<<dim3(Tn / 128, BHn), 256>>>();
    // 5. AV, split-s, cp.async double-buffered, RED accumulate
    av16<<<dim3(Tn / 128, 8, BHn), 256, smemAV>>>();
    // 6. Output projection + residual 1 (A fp32 -> half in-stage)
    gemm128<1, 1><<<dim3(Cn / 128, BTn / 128), 512>>>(p_attn, p_wpt, b_proj, x, p_x1, Cn, Cn);
    // 7. LN2 -> fp16
    ln_kernel<<<BTn, 128>>>(p_x1, g2, be2, p_h);
    // 8. MLP up + relu
    gemm128<0, 0><<<dim3(C4n / 128, BTn / 128), 512>>>(p_h, p_w1t, b1, nullptr, p_f1h, C4n, Cn);
    // 9. MLP down + residual 2 -> out
    gemm128<1, 0><<<dim3(Cn / 128, BTn / 128), 512>>>(p_f1h, p_w2t, b2, p_x1, out, Cn, C4n);
}

// round 14
// speedup vs baseline: 1.0777x; 1.0777x over previous
#include <cuda_runtime.h>
#include <cuda_fp16.h>
#include <math.h>

#define Bv   4
#define Tn   2048
#define Cn   384
#define Hn   6
#define HSn  64
#define BTn  8192
#define BHn  24
#define C4n  1536

// ------------------------- scratch (static device globals) -------------------------
__device__ __half g_h[BTn * Cn];                     // LN output fp16
__device__ __half g_qh[BHn * Tn * HSn];              // Q fp16 [bh][t][d]
__device__ __half g_kh[BHn * Tn * HSn];              // K fp16 [bh][s][d]
__device__ float  g_v[BHn * Tn * HSn];               // V fp32 [bh][s][d]
__device__ __half g_vt[BHn * HSn * Tn];              // V'/Z transposed fp16 [bh][d][s]
__device__ float  g_z[BHn * Tn];                     // per-key sum of exp(S)
__device__ __half g_swt[(size_t)BHn * Tn * Tn];      // weights exp(S) fp16, layout [bh][t][s]
__device__ float  g_attn[BTn * Cn];                  // attention out fp32 (RED target)
__device__ float  g_x1[BTn * Cn];
__device__ __half g_f1h[BTn * C4n];                  // MLP hidden fp16
// fp16 transposed weights Bt[N][K]
__device__ __half g_wqkvt[3 * Hn * HSn * Cn];        // [sel][h][d][c] == [1152][384]
__device__ __half g_wpt[Cn * Cn];                    // [n][k]
__device__ __half g_w1t[C4n * Cn];                   // [n 1536][k 384]
__device__ __half g_w2t[Cn * C4n];                   // [n 384][k 1536]

#define SCALE 0.05103103630798287f       // 384^-0.5

// ------------------------- mma / async helpers -------------------------
__device__ __forceinline__ void mma16(float* c, const unsigned* a, const unsigned* b) {
    asm volatile(
        "mma.sync.aligned.m16n8k16.row.col.f32.f16.f16.f32 "
        "{%0,%1,%2,%3}, {%4,%5,%6,%7}, {%8,%9}, {%0,%1,%2,%3};\n"
        : "+f"(c[0]), "+f"(c[1]), "+f"(c[2]), "+f"(c[3])
        : "r"(a[0]), "r"(a[1]), "r"(a[2]), "r"(a[3]), "r"(b[0]), "r"(b[1]));
}

__device__ __forceinline__ void red2(float* p, float x, float y) {
    asm volatile("red.global.add.v2.f32 [%0], {%1,%2};" :: "l"(p), "f"(x), "f"(y) : "memory");
}

__device__ __forceinline__ void cp16(void* dst, const void* src) {
    unsigned d = (unsigned)__cvta_generic_to_shared(dst);
    asm volatile("cp.async.cg.shared.global [%0], [%1], 16;" :: "r"(d), "l"(src) : "memory");
}
#define CP_COMMIT() asm volatile("cp.async.commit_group;" ::: "memory")
#define CP_WAIT1()  asm volatile("cp.async.wait_group 1;" ::: "memory")
#define CP_WAIT0()  asm volatile("cp.async.wait_group 0;" ::: "memory")

// ------------------------- fused weight prep: all transposes+fp16 in ONE kernel -------------------------
// tiles: [0,432) qkv, [432,576) w_proj, [576,1152) w1, [1152,1728) w2. block (32,8).
__global__ void prep_weights(const float* __restrict__ wq, const float* __restrict__ wk,
                             const float* __restrict__ wv, const float* __restrict__ wp,
                             const float* __restrict__ w1, const float* __restrict__ w2) {
    __shared__ float tl[32][33];
    int bid = blockIdx.x;
    const float* in;
    __half* out;
    int K, N, n0, k0;
    if (bid < 432) {
        int mat = bid / 24, t = bid % 24;
        int sel = mat / Hn, hh = mat % Hn;
        in = (sel == 0 ? wq : sel == 1 ? wk : wv) + hh * Cn * HSn;
        out = g_wqkvt + (size_t)mat * HSn * Cn;
        K = Cn; N = HSn;
        n0 = (t & 1) * 32; k0 = (t >> 1) * 32;
    } else if (bid < 576) {
        int t = bid - 432;
        in = wp; out = g_wpt; K = Cn; N = Cn;
        n0 = (t % 12) * 32; k0 = (t / 12) * 32;
    } else if (bid < 1152) {
        int t = bid - 576;
        in = w1; out = g_w1t; K = Cn; N = C4n;
        n0 = (t % 48) * 32; k0 = (t / 48) * 32;
    } else {
        int t = bid - 1152;
        in = w2; out = g_w2t; K = C4n; N = Cn;
        n0 = (t % 12) * 32; k0 = (t / 12) * 32;
    }
    int tx = threadIdx.x, ty = threadIdx.y;
    #pragma unroll
    for (int i = 0; i < 4; i++)
        tl[ty + i * 8][tx] = in[(size_t)(k0 + ty + i * 8) * N + n0 + tx];
    __syncthreads();
    #pragma unroll
    for (int i = 0; i < 4; i++)
        out[(size_t)(n0 + ty + i * 8) * K + k0 + tx] = __float2half(tl[tx][ty + i * 8]);
}

// ------------------------- LayerNorm (fp32 in, fp16 out) -------------------------
__global__ void ln_kernel(const float* __restrict__ in, const float* __restrict__ gamma,
                          const float* __restrict__ beta, __half* __restrict__ out) {
    int row = blockIdx.x;
    int tid = threadIdx.x;
    const float* p = in + row * Cn;
    float v0 = p[tid], v1 = p[tid + 128], v2 = p[tid + 256];
    float s = v0 + v1 + v2;
    __shared__ float red[4];
    #pragma unroll
    for (int o = 16; o > 0; o >>= 1) s += __shfl_xor_sync(0xffffffffu, s, o);
    if ((tid & 31) == 0) red[tid >> 5] = s;
    __syncthreads();
    float mean = (red[0] + red[1] + red[2] + red[3]) * (1.0f / Cn);
    __syncthreads();
    float d0 = v0 - mean, d1 = v1 - mean, d2 = v2 - mean;
    float q = d0 * d0 + d1 * d1 + d2 * d2;
    #pragma unroll
    for (int o = 16; o > 0; o >>= 1) q += __shfl_xor_sync(0xffffffffu, q, o);
    if ((tid & 31) == 0) red[tid >> 5] = q;
    __syncthreads();
    float var = (red[0] + red[1] + red[2] + red[3]) * (1.0f / Cn);
    float r = rsqrtf(var + 1e-5f);
    __half* o = out + row * Cn;
    o[tid]       = __float2half(d0 * r * gamma[tid]       + beta[tid]);
    o[tid + 128] = __float2half(d1 * r * gamma[tid + 128] + beta[tid + 128]);
    o[tid + 256] = __float2half(d2 * r * gamma[tid + 256] + beta[tid + 256]);
}

// ------------------------- fp16 GEMM 128x128: C[M,N] = A[M,K] @ Bt[N,K]^T -------------------------
// 512 threads, 16 warps (4m x 4n), warp tile 32x32, BK=64.
// AF32: A is fp32, converted to half during smem stage.
// EPI 0: bias+relu -> half. EPI 1: bias+resid -> float.
template <int EPI, int AF32>
__global__ __launch_bounds__(512)
void gemm128(const void* __restrict__ Ain, const __half* __restrict__ Bt,
             const float* __restrict__ bias, const float* __restrict__ resid,
             void* __restrict__ Co, int N, int K) {
    __shared__ __half As[128][72];
    __shared__ __half Bs[128][72];
    int m0 = blockIdx.y * 128, n0 = blockIdx.x * 128;
    int tid = threadIdx.x, l = tid & 31, w = tid >> 5;
    int wm = (w & 3) * 32, wn = (w >> 2) * 32;
    int g = l >> 2, tg = l & 3;
    const unsigned* A32 = (const unsigned*)As;
    const unsigned* B32 = (const unsigned*)Bs;
    float acc[2][4][4] = {};
    for (int k0 = 0; k0 < K; k0 += 64) {
        if (AF32) {
            const float* Af = (const float*)Ain;
            #pragma unroll
            for (int i = 0; i < 4; i++) {
                int idx = tid + i * 512;
                int r = idx >> 4, c4 = (idx & 15) * 4;
                float4 v = *(const float4*)&Af[(size_t)(m0 + r) * K + k0 + c4];
                *(__half2*)&As[r][c4]     = __floats2half2_rn(v.x, v.y);
                *(__half2*)&As[r][c4 + 2] = __floats2half2_rn(v.z, v.w);
            }
        } else {
            const __half* Ah = (const __half*)Ain;
            #pragma unroll
            for (int i = 0; i < 2; i++) {
                int idx = tid + i * 512;
                int r = idx >> 3, cv = (idx & 7) * 8;
                *(float4*)&As[r][cv] = *(const float4*)&Ah[(size_t)(m0 + r) * K + k0 + cv];
            }
        }
        #pragma unroll
        for (int i = 0; i < 2; i++) {
            int idx = tid + i * 512;
            int r = idx >> 3, cv = (idx & 7) * 8;
            *(float4*)&Bs[r][cv] = *(const float4*)&Bt[(size_t)(n0 + r) * K + k0 + cv];
        }
        __syncthreads();
        #pragma unroll
        for (int kk = 0; kk < 64; kk += 16) {
            int kw = kk >> 1;
            unsigned a[2][4], b[4][2];
            #pragma unroll
            for (int im = 0; im < 2; im++) {
                int r = wm + im * 16;
                a[im][0] = A32[(r + g) * 36 + kw + tg];
                a[im][1] = A32[(r + 8 + g) * 36 + kw + tg];
                a[im][2] = A32[(r + g) * 36 + kw + 4 + tg];
                a[im][3] = A32[(r + 8 + g) * 36 + kw + 4 + tg];
            }
            #pragma unroll
            for (int jn = 0; jn < 4; jn++) {
                int c = wn + jn * 8;
                b[jn][0] = B32[(c + g) * 36 + kw + tg];
                b[jn][1] = B32[(c + g) * 36 + kw + 4 + tg];
            }
            #pragma unroll
            for (int im = 0; im < 2; im++)
                #pragma unroll
                for (int jn = 0; jn < 4; jn++) mma16(acc[im][jn], a[im], b[jn]);
        }
        __syncthreads();
    }
    #pragma unroll
    for (int im = 0; im < 2; im++) {
        #pragma unroll
        for (int hh = 0; hh < 2; hh++) {
            int r0 = m0 + wm + im * 16 + g + hh * 8;
            #pragma unroll
            for (int jn = 0; jn < 4; jn++) {
                int c = n0 + wn + jn * 8 + tg * 2;
                float v0 = acc[im][jn][hh * 2]     + bias[c];
                float v1 = acc[im][jn][hh * 2 + 1] + bias[c + 1];
                if (EPI == 0) {
                    v0 = fmaxf(v0, 0.f); v1 = fmaxf(v1, 0.f);
                    *(__half2*)&((__half*)Co)[(size_t)r0 * N + c] = __floats2half2_rn(v0, v1);
                } else {
                    v0 += resid[(size_t)r0 * N + c];
                    v1 += resid[(size_t)r0 * N + c + 1];
                    *(float2*)&((float*)Co)[(size_t)r0 * N + c] = make_float2(v0, v1);
                }
            }
        }
    }
}

// ------------------------- QKV as one GEMM [8192,384] @ [1152,384]^T, routed epilogue -------------------------
__global__ __launch_bounds__(512)
void qkv128() {
    __shared__ __half As[128][72];
    __shared__ __half Bs[128][72];
    int m0 = blockIdx.y * 128, n0 = blockIdx.x * 128;
    int tid = threadIdx.x, l = tid & 31, w = tid >> 5;
    int wm = (w & 3) * 32, wn = (w >> 2) * 32;
    int g = l >> 2, tg = l & 3;
    const unsigned* A32 = (const unsigned*)As;
    const unsigned* B32 = (const unsigned*)Bs;
    float acc[2][4][4] = {};
    for (int k0 = 0; k0 < Cn; k0 += 64) {
        #pragma unroll
        for (int i = 0; i < 2; i++) {
            int idx = tid + i * 512;
            int r = idx >> 3, cv = (idx & 7) * 8;
            *(float4*)&As[r][cv] = *(const float4*)&g_h[(size_t)(m0 + r) * Cn + k0 + cv];
            *(float4*)&Bs[r][cv] = *(const float4*)&g_wqkvt[(size_t)(n0 + r) * Cn + k0 + cv];
        }
        __syncthreads();
        #pragma unroll
        for (int kk = 0; kk < 64; kk += 16) {
            int kw = kk >> 1;
            unsigned a[2][4], b[4][2];
            #pragma unroll
            for (int im = 0; im < 2; im++) {
                int r = wm + im * 16;
                a[im][0] = A32[(r + g) * 36 + kw + tg];
                a[im][1] = A32[(r + 8 + g) * 36 + kw + tg];
                a[im][2] = A32[(r + g) * 36 + kw + 4 + tg];
                a[im][3] = A32[(r + 8 + g) * 36 + kw + 4 + tg];
            }
            #pragma unroll
            for (int jn = 0; jn < 4; jn++) {
                int c = wn + jn * 8;
                b[jn][0] = B32[(c + g) * 36 + kw + tg];
                b[jn][1] = B32[(c + g) * 36 + kw + 4 + tg];
            }
            #pragma unroll
            for (int im = 0; im < 2; im++)
                #pragma unroll
                for (int jn = 0; jn < 4; jn++) mma16(acc[im][jn], a[im], b[jn]);
        }
        __syncthreads();
    }
    int nbase = n0 + wn;
    int sel = nbase / (Hn * HSn);
    int nn  = nbase % (Hn * HSn);
    int hh  = nn / HSn;
    int dbase = nn % HSn;
    #pragma unroll
    for (int im = 0; im < 2; im++) {
        #pragma unroll
        for (int hf = 0; hf < 2; hf++) {
            int m = m0 + wm + im * 16 + g + hf * 8;
            int b = m >> 11, t = m & (Tn - 1);
            size_t rowoff = ((size_t)(b * Hn + hh) * Tn + t) * HSn;
            if (sel == 2) {
                float* orow = g_v + rowoff;
                #pragma unroll
                for (int jn = 0; jn < 4; jn++) {
                    int d = dbase + jn * 8 + tg * 2;
                    *(float2*)&orow[d] =
                        make_float2(acc[im][jn][hf * 2], acc[im][jn][hf * 2 + 1]);
                }
            } else {
                __half* orow = (sel == 0 ? g_qh : g_kh) + rowoff;
                #pragma unroll
                for (int jn = 0; jn < 4; jn++) {
                    int d = dbase + jn * 8 + tg * 2;
                    *(__half2*)&orow[d] =
                        __floats2half2_rn(acc[im][jn][hf * 2], acc[im][jn][hf * 2 + 1]);
                }
            }
        }
    }
}

// ------------------------- wsum16 (R11 form): Wt[t][s] = exp(scale*Q[t]·K[s]) fp16, Z[s] sums -------------------------
__global__ __launch_bounds__(256)
void wsum16() {
    __shared__ __half Qs[128][72];
    __shared__ __half Ks[128][72];
    int tT = blockIdx.x, sT = blockIdx.y, bh = blockIdx.z;
    if (tT < sT) return;
    const __half* Qp = g_qh + (size_t)bh * Tn * HSn + (size_t)tT * 128 * HSn;
    const __half* Kp = g_kh + (size_t)bh * Tn * HSn + (size_t)sT * 128 * HSn;
    __half* Wr = g_swt + (size_t)bh * Tn * Tn;
    int tid = threadIdx.x, l = tid & 31, w = tid >> 5;
    int g = l >> 2, tg = l & 3;
    #pragma unroll
    for (int i = 0; i < 4; i++) {
        int idx = tid + i * 256;
        int r = idx >> 3, cv = (idx & 7) * 8;
        *(float4*)&Qs[r][cv] = *(const float4*)&Qp[(size_t)r * HSn + cv];
        *(float4*)&Ks[r][cv] = *(const float4*)&Kp[(size_t)r * HSn + cv];
    }
    __syncthreads();
    int wm = (w & 3) * 32, wn = (w >> 2) * 64;
    const unsigned* Q32 = (const unsigned*)Qs;
    const unsigned* K32 = (const unsigned*)Ks;
    float acc[2][8][4] = {};
    #pragma unroll
    for (int kk = 0; kk < 64; kk += 16) {
        int kw = kk >> 1;
        unsigned a[2][4], b[8][2];
        #pragma unroll
        for (int im = 0; im < 2; im++) {
            int r = wm + im * 16;
            a[im][0] = Q32[(r + g) * 36 + kw + tg];
            a[im][1] = Q32[(r + 8 + g) * 36 + kw + tg];
            a[im][2] = Q32[(r + g) * 36 + kw + 4 + tg];
            a[im][3] = Q32[(r + 8 + g) * 36 + kw + 4 + tg];
        }
        #pragma unroll
        for (int jn = 0; jn < 8; jn++) {
            int c = wn + jn * 8;
            b[jn][0] = K32[(c + g) * 36 + kw + tg];
            b[jn][1] = K32[(c + g) * 36 + kw + 4 + tg];
        }
        #pragma unroll
        for (int im = 0; im < 2; im++)
            #pragma unroll
            for (int jn = 0; jn < 8; jn++) mma16(acc[im][jn], a[im], b[jn]);
    }
    bool diag = (tT == sT);
    #pragma unroll
    for (int jn = 0; jn < 8; jn++) {
        int s_glob = sT * 128 + wn + jn * 8 + 2 * tg;
        float z0 = 0.f, z1 = 0.f;
        #pragma unroll
        for (int im = 0; im < 2; im++) {
            #pragma unroll
            for (int hh = 0; hh < 2; hh++) {
                int t_glob = tT * 128 + wm + im * 16 + g + hh * 8;
                float e0 = __expf(acc[im][jn][hh * 2]     * SCALE);
                float e1 = __expf(acc[im][jn][hh * 2 + 1] * SCALE);
                if (diag) {
                    if (t_glob < s_glob)     e0 = 0.f;
                    if (t_glob < s_glob + 1) e1 = 0.f;
                }
                *(__half2*)&Wr[(size_t)t_glob * Tn + s_glob] = __floats2half2_rn(e0, e1);
                z0 += e0; z1 += e1;
            }
        }
        z0 += __shfl_xor_sync(0xffffffffu, z0, 4);
        z1 += __shfl_xor_sync(0xffffffffu, z1, 4);
        z0 += __shfl_xor_sync(0xffffffffu, z0, 8);
        z1 += __shfl_xor_sync(0xffffffffu, z1, 8);
        z0 += __shfl_xor_sync(0xffffffffu, z0, 16);
        z1 += __shfl_xor_sync(0xffffffffu, z1, 16);
        if (g == 0) red2(&g_z[bh * Tn + s_glob], z0, z1);
    }
}

// ------------------------- vscale_t: Vt[d][s] = fp16( V[s][d] / Z[s] ) -------------------------
__global__ void vscale_t() {
    __shared__ float tile[128][65];
    int s0 = blockIdx.x * 128, bh = blockIdx.y;
    int tid = threadIdx.x;
    const float* Vb = g_v + ((size_t)bh * Tn + s0) * HSn;
    #pragma unroll
    for (int i = 0; i < 8; i++) {
        int idx = tid + i * 256;
        int r = idx >> 4, cv = (idx & 15) * 4;
        float inv = __fdividef(1.0f, g_z[bh * Tn + s0 + r]);
        float4 v = *(const float4*)&Vb[(size_t)r * HSn + cv];
        tile[r][cv + 0] = v.x * inv; tile[r][cv + 1] = v.y * inv;
        tile[r][cv + 2] = v.z * inv; tile[r][cv + 3] = v.w * inv;
    }
    __syncthreads();
    #pragma unroll
    for (int i = 0; i < 16; i++) {
        int idx = tid + i * 256;
        int d = idx >> 6, sp = idx & 63;
        __half2 h = __floats2half2_rn(tile[2 * sp][d], tile[2 * sp + 1][d]);
        *(__half2*)&g_vt[((size_t)bh * HSn + d) * Tn + s0 + 2 * sp] = h;
    }
}

// ------------------------- av16: out[t][d] = sum_s Wt[t][s] * Vt[d][s], cp.async double-buffered -------------------------
#define WTILE (128 * 72)
#define VTILE (64 * 72)
__global__ __launch_bounds__(256, 2)
void av16() {
    extern __shared__ __half smav[];
    __half* Wb[2] = {smav, smav + WTILE};
    __half* Vb[2] = {smav + 2 * WTILE, smav + 2 * WTILE + VTILE};
    int tT = blockIdx.x, sc = blockIdx.y, bh = blockIdx.z;
    int t0 = tT * 128;
    int sBase = sc * 256;
    if (sBase >= t0 + 128) return;
    int limit = min(sBase + 256, t0 + 128);
    int nch = (limit - sBase) >> 6;
    int b = bh / Hn, h = bh % Hn;
    const __half* Wg = g_swt + (size_t)bh * Tn * Tn;
    const __half* Vg = g_vt + (size_t)bh * HSn * Tn;
    int tid = threadIdx.x, l = tid & 31, w = tid >> 5;
    int g = l >> 2, tg = l & 3;
    int wm = (w & 3) * 32, wn = (w >> 2) * 32;
    float acc[2][4][4] = {};
    {
        int s0 = sBase;
        #pragma unroll
        for (int i = 0; i < 4; i++) {
            int idx = tid + i * 256;
            int r = idx >> 3, cv = (idx & 7) * 8;
            cp16(Wb[0] + r * 72 + cv, &Wg[(size_t)(t0 + r) * Tn + s0 + cv]);
        }
        #pragma unroll
        for (int i = 0; i < 2; i++) {
            int idx = tid + i * 256;
            int r = idx >> 3, cv = (idx & 7) * 8;
            cp16(Vb[0] + r * 72 + cv, &Vg[(size_t)r * Tn + s0 + cv]);
        }
        CP_COMMIT();
    }
    for (int j = 0; j < nch; j++) {
        if (j + 1 < nch) {
            int s0 = sBase + (j + 1) * 64, buf = (j + 1) & 1;
            #pragma unroll
            for (int i = 0; i < 4; i++) {
                int idx = tid + i * 256;
                int r = idx >> 3, cv = (idx & 7) * 8;
                cp16(Wb[buf] + r * 72 + cv, &Wg[(size_t)(t0 + r) * Tn + s0 + cv]);
            }
            #pragma unroll
            for (int i = 0; i < 2; i++) {
                int idx = tid + i * 256;
                int r = idx >> 3, cv = (idx & 7) * 8;
                cp16(Vb[buf] + r * 72 + cv, &Vg[(size_t)r * Tn + s0 + cv]);
            }
            CP_COMMIT();
            CP_WAIT1();
        } else {
            CP_WAIT0();
        }
        __syncthreads();
        const unsigned* W32 = (const unsigned*)Wb[j & 1];
        const unsigned* V32 = (const unsigned*)Vb[j & 1];
        #pragma unroll
        for (int kk = 0; kk < 64; kk += 16) {
            int kw = kk >> 1;
            unsigned a[2][4], bf[4][2];
            #pragma unroll
            for (int im = 0; im < 2; im++) {
                int r = wm + im * 16;
                a[im][0] = W32[(r + g) * 36 + kw + tg];
                a[im][1] = W32[(r + 8 + g) * 36 + kw + tg];
                a[im][2] = W32[(r + g) * 36 + kw + 4 + tg];
                a[im][3] = W32[(r + 8 + g) * 36 + kw + 4 + tg];
            }
            #pragma unroll
            for (int jn = 0; jn < 4; jn++) {
                int c = wn + jn * 8;
                bf[jn][0] = V32[(c + g) * 36 + kw + tg];
                bf[jn][1] = V32[(c + g) * 36 + kw + 4 + tg];
            }
            #pragma unroll
            for (int im = 0; im < 2; im++)
                #pragma unroll
                for (int jn = 0; jn < 4; jn++) mma16(acc[im][jn], a[im], bf[jn]);
        }
        __syncthreads();
    }
    #pragma unroll
    for (int im = 0; im < 2; im++) {
        #pragma unroll
        for (int hh = 0; hh < 2; hh++) {
            int t = t0 + wm + im * 16 + g + hh * 8;
            float* orow = g_attn + (size_t)(b * Tn + t) * Cn + h * HSn;
            #pragma unroll
            for (int jn = 0; jn < 4; jn++) {
                int d = wn + jn * 8 + tg * 2;
                red2(&orow[d], acc[im][jn][hh * 2], acc[im][jn][hh * 2 + 1]);
            }
        }
    }
}

// ------------------------- launch -------------------------
extern "C" void kernel_launch(void* const* d_in, const int* in_sizes, int n_in,
                              void* d_out, int out_size) {
    const float* x      = (const float*)d_in[0];
    const float* wq     = (const float*)d_in[1];
    const float* wk     = (const float*)d_in[2];
    const float* wv     = (const float*)d_in[3];
    const float* w_proj = (const float*)d_in[4];
    const float* b_proj = (const float*)d_in[5];
    const float* w1     = (const float*)d_in[6];
    const float* b1     = (const float*)d_in[7];
    const float* w2     = (const float*)d_in[8];
    const float* b2     = (const float*)d_in[9];
    const float* g1     = (const float*)d_in[10];
    const float* be1    = (const float*)d_in[11];
    const float* g2     = (const float*)d_in[12];
    const float* be2    = (const float*)d_in[13];
    float* out = (float*)d_out;

    __half *p_h, *p_f1h, *p_wpt, *p_w1t, *p_w2t;
    float *p_x1, *p_attn, *p_z;
    cudaGetSymbolAddress((void**)&p_h,     g_h);
    cudaGetSymbolAddress((void**)&p_x1,    g_x1);
    cudaGetSymbolAddress((void**)&p_attn,  g_attn);
    cudaGetSymbolAddress((void**)&p_f1h,   g_f1h);
    cudaGetSymbolAddress((void**)&p_z,     g_z);
    cudaGetSymbolAddress((void**)&p_wpt,   g_wpt);
    cudaGetSymbolAddress((void**)&p_w1t,   g_w1t);
    cudaGetSymbolAddress((void**)&p_w2t,   g_w2t);

    int smemAV = (2 * WTILE + 2 * VTILE) * (int)sizeof(__half);   // 55296
    cudaFuncSetAttribute(av16, cudaFuncAttributeMaxDynamicSharedMemorySize, smemAV);

    // 0. zero accumulators + fused weight prep (one kernel)
    cudaMemsetAsync(p_z, 0, (size_t)BHn * Tn * sizeof(float));
    cudaMemsetAsync(p_attn, 0, (size_t)BTn * Cn * sizeof(float));
    prep_weights<<<1728, dim3(32, 8)>>>(wq, wk, wv, w_proj, w1, w2);
    // 1. LN1 -> fp16
    ln_kernel<<<BTn, 128>>>(x, g1, be1, p_h);
    // 2. QKV as one 128x128 GEMM with routed epilogue
    qkv128<<<dim3(9, BTn / 128), 512>>>();
    // 3. Weights Wt[t][s] fp16 + Z row sums
    wsum16<<<dim3(Tn / 128, Tn / 128, BHn), 256>>>();
    // 4. V'/Z transpose fp16
    vscale_t<<<dim3(Tn / 128, BHn), 256>>>();
    // 5. AV, split-s, cp.async double-buffered, RED accumulate
    av16<<<dim3(Tn / 128, 8, BHn), 256, smemAV>>>();
    // 6. Output projection + residual 1 (A fp32 -> half in-stage)
    gemm128<1, 1><<<dim3(Cn / 128, BTn / 128), 512>>>(p_attn, p_wpt, b_proj, x, p_x1, Cn, Cn);
    // 7. LN2 -> fp16
    ln_kernel<<<BTn, 128>>>(p_x1, g2, be2, p_h);
    // 8. MLP up + relu
    gemm128<0, 0><<<dim3(C4n / 128, BTn / 128), 512>>>(p_h, p_w1t, b1, nullptr, p_f1h, C4n, Cn);
    // 9. MLP down + residual 2 -> out
    gemm128<1, 0><<<dim3(Cn / 128, BTn / 128), 512>>>(p_f1h, p_w2t, b2, p_x1, out, Cn, C4n);
}